// round 11
// baseline (speedup 1.0000x reference)
#include <cuda_runtime.h>
#include <cstdint>

#define ROWS 32768
#define TPB  128            // 4 warps
#define RPB  64             // rows per block (scanned by warps 0-1)
#define XS   68             // padded row stride in smem (floats): 272B

__device__ __forceinline__ unsigned long long fma2(unsigned long long a,
                                                   unsigned long long b,
                                                   unsigned long long c) {
    unsigned long long d;
    asm("fma.rn.f32x2 %0, %1, %2, %3;" : "=l"(d) : "l"(a), "l"(b), "l"(c));
    return d;
}
__device__ __forceinline__ unsigned long long pack2(float lo, float hi) {
    unsigned long long d;
    asm("mov.b64 %0, {%1, %2};" : "=l"(d) : "f"(lo), "f"(hi));
    return d;
}
__device__ __forceinline__ void unpack2(unsigned long long v, float& lo, float& hi) {
    asm("mov.b64 {%0, %1}, %2;" : "=f"(lo), "=f"(hi) : "l"(v));
}

// tanh(x) = 1 - 2/(exp(2x)+1) via ex2.approx + rcp.approx (~1e-6 rel err)
__device__ __forceinline__ float fast_tanh(float x) {
    float e, r;
    asm("ex2.approx.f32 %0, %1;" : "=f"(e) : "f"(x * 2.8853900817779268f));
    asm("rcp.approx.f32 %0, %1;" : "=f"(r) : "f"(e + 1.0f));
    return fmaf(-2.0f, r, 1.0f);
}

__global__ __launch_bounds__(TPB)
void metak_kernel(const int*   __restrict__ vals,
                  const float* __restrict__ dist,
                  const float* __restrict__ fc2_w1,   // [64,32]
                  const float* __restrict__ fc2_b1,   // [32]
                  const float* __restrict__ fc2_w2,   // [32,2]
                  const float* __restrict__ fc2_b2,   // [2]
                  const float* __restrict__ fc1_w1,   // [2,4]
                  const float* __restrict__ fc1_b1,   // [4]
                  const float* __restrict__ fc1_w2,   // [4,1]
                  const float* __restrict__ fc1_b2,   // [1]
                  float*       __restrict__ out)
{
    // Staged features; after a row's GEMV its h[32] overlays floats [0..31]
    // of the same row. 64*68*4 = 17408 B.
    __shared__ __align__(16) float xs[RPB * XS];
    __shared__ __align__(8)  float sw2[64];         // fc2_w2 [32][2]
    __shared__ float shead[19];  // [0..7]=f1w1 [8..11]=f1b1 [12..15]=f1w2 [16]=f1b2 [17,18]=b2

    const int tid  = threadIdx.x;
    const int lane = tid & 31;
    const int wid  = tid >> 5;
    const int rowblock = blockIdx.x * RPB;

    if (tid < 64) sw2[tid] = fc2_w2[tid];
    if (tid < 8)        shead[tid] = fc1_w1[tid];
    else if (tid < 12)  shead[tid] = fc1_b1[tid - 8];
    else if (tid < 16)  shead[tid] = fc1_w2[tid - 12];
    else if (tid == 16) shead[16]  = fc1_b2[0];
    else if (tid == 17) shead[17]  = fc2_b2[0];
    else if (tid == 18) shead[18]  = fc2_b2[1];

    // ========== Phase 1: threads 0..63 each scan ONE row ==========
    if (tid < RPB) {
        const int r = rowblock + tid;
        const float4* dp = reinterpret_cast<const float4*>(dist) + (size_t)r * 8;
        const int4*   vp = reinterpret_cast<const int4*>(vals) + (size_t)r * 8;

        float4* xv = reinterpret_cast<float4*>(xs + tid * XS);

        float4 d0 = dp[0], d1 = dp[1], d2 = dp[2], d3 = dp[3],
               d4 = dp[4], d5 = dp[5], d6 = dp[6], d7 = dp[7];
        int4   v0 = vp[0], v1 = vp[1], v2 = vp[2], v3 = vp[3],
               v4 = vp[4], v5 = vp[5], v6 = vp[6], v7 = vp[7];

        xv[0] = d0; xv[1] = d1; xv[2] = d2; xv[3] = d3;
        xv[4] = d4; xv[5] = d5; xv[6] = d6; xv[7] = d7;

        // prefix distinct-nonzero-label counts (labels in [0,100); bit0 preset)
        unsigned long long m0 = 1ull, m1 = 0ull;
        int cnt = 0;
        int4 vv4[8] = {v0, v1, v2, v3, v4, v5, v6, v7};
#pragma unroll
        for (int i = 0; i < 8; i++) {
            float t0, t1, t2, t3;
#pragma unroll
            for (int e = 0; e < 4; e++) {
                int vv = (e == 0) ? vv4[i].x : (e == 1) ? vv4[i].y
                       : (e == 2) ? vv4[i].z : vv4[i].w;
                unsigned long long bit = 1ull << (vv & 63);
                bool hi = (vv & 64) != 0;
                unsigned long long cur = hi ? m1 : m0;
                cnt += (int)((cur & bit) == 0ull);
                cur |= bit;
                if (hi) m1 = cur; else m0 = cur;
                float cf = (float)cnt;
                if (e == 0) t0 = cf; else if (e == 1) t1 = cf;
                else if (e == 2) t2 = cf; else t3 = cf;
            }
            xv[8 + i] = make_float4(t0, t1, t2, t3);
        }
    }

    // ---- per-lane weight column, packed over k pairs (after scan: low reg peak)
    unsigned long long wpk[32];
#pragma unroll
    for (int m = 0; m < 32; m++)
        wpk[m] = pack2(fc2_w1[(2 * m) * 32 + lane],
                       fc2_w1[(2 * m + 1) * 32 + lane]);
    const float b1 = fc2_b1[lane];

    __syncthreads();

    // ===== Phase 2a: each warp sweeps 16 rows, 2 rows x split-k = 4 chains =====
    const int wrow0 = wid * 16;
#pragma unroll 1
    for (int p = 0; p < 8; p++) {
        const int ra = wrow0 + 2 * p;
        const ulonglong2* xa = reinterpret_cast<const ulonglong2*>(xs + ra * XS);
        const ulonglong2* xb = reinterpret_cast<const ulonglong2*>(xs + (ra + 1) * XS);

        unsigned long long a0 = 0ull, a1 = 0ull, b0 = 0ull, b1c = 0ull;
#pragma unroll
        for (int c = 0; c < 8; c++) {
            ulonglong2 A0 = xa[c];                   // k pairs 2c, 2c+1
            ulonglong2 B0 = xb[c];
            ulonglong2 A1 = xa[8 + c];
            ulonglong2 B1 = xb[8 + c];
            a0  = fma2(A0.x, wpk[2 * c],      a0);
            b0  = fma2(B0.x, wpk[2 * c],      b0);
            a1  = fma2(A1.x, wpk[16 + 2 * c], a1);
            b1c = fma2(B1.x, wpk[16 + 2 * c], b1c);
            a0  = fma2(A0.y, wpk[2 * c + 1],      a0);
            b0  = fma2(B0.y, wpk[2 * c + 1],      b0);
            a1  = fma2(A1.y, wpk[16 + 2 * c + 1], a1);
            b1c = fma2(B1.y, wpk[16 + 2 * c + 1], b1c);
        }
        float x0, x1, x2, x3, y0, y1, y2, y3;
        unpack2(a0, x0, x1);
        unpack2(a1, x2, x3);
        unpack2(b0, y0, y1);
        unpack2(b1c, y2, y3);
        float hA = fast_tanh((x0 + x1) + (x2 + x3) + b1);
        float hB = fast_tanh((y0 + y1) + (y2 + y3) + b1);
        xs[ra * XS + lane]       = hA;    // overlay h into dead x region
        xs[(ra + 1) * XS + lane] = hB;
    }

    __syncwarp();   // h of this warp's rows written and read by same warp

    // ===== Phase 2b: lanes 0..15 each finish one row — no shuffles =====
    if (lane < 16) {
        const float* hrow = xs + (wrow0 + lane) * XS;
        float o0 = shead[17], o1 = shead[18];
#pragma unroll
        for (int j = 0; j < 32; j++) {
            float hj = hrow[j];
            o0 = fmaf(hj, sw2[2 * j],     o0);
            o1 = fmaf(hj, sw2[2 * j + 1], o1);
        }

        float r = shead[16];
#pragma unroll
        for (int c = 0; c < 4; c++) {
            float t = fast_tanh(fmaf(o1, shead[4 + c],
                                fmaf(o0, shead[c], shead[8 + c])));
            r = fmaf(t, shead[12 + c], r);
        }

        float* op = out + (size_t)(rowblock + wrow0 + lane) * 3;
        op[0] = o0;
        op[1] = o1;
        op[2] = r;
    }
}

extern "C" void kernel_launch(void* const* d_in, const int* in_sizes, int n_in,
                              void* d_out, int out_size)
{
    const int*   vals   = (const int*)  d_in[0];
    const float* dist   = (const float*)d_in[1];
    const float* fc2_w1 = (const float*)d_in[2];
    const float* fc2_b1 = (const float*)d_in[3];
    const float* fc2_w2 = (const float*)d_in[4];
    const float* fc2_b2 = (const float*)d_in[5];
    const float* fc1_w1 = (const float*)d_in[6];
    const float* fc1_b1 = (const float*)d_in[7];
    const float* fc1_w2 = (const float*)d_in[8];
    const float* fc1_b2 = (const float*)d_in[9];
    float* out = (float*)d_out;

    const int blocks = ROWS / RPB;   // 512
    metak_kernel<<<blocks, TPB>>>(vals, dist,
                                  fc2_w1, fc2_b1, fc2_w2, fc2_b2,
                                  fc1_w1, fc1_b1, fc1_w2, fc1_b2,
                                  out);
}

// round 13
// speedup vs baseline: 1.4068x; 1.4068x over previous
#include <cuda_runtime.h>
#include <cstdint>

#define ROWS 32768
#define TPB  128            // 4 warps
#define RPB  64             // rows per block (scanned by warps 0-1)
#define XS   68             // padded row stride in smem (floats): 272B

__device__ __forceinline__ unsigned long long fma2(unsigned long long a,
                                                   unsigned long long b,
                                                   unsigned long long c) {
    unsigned long long d;
    asm("fma.rn.f32x2 %0, %1, %2, %3;" : "=l"(d) : "l"(a), "l"(b), "l"(c));
    return d;
}
__device__ __forceinline__ unsigned long long pack2(float lo, float hi) {
    unsigned long long d;
    asm("mov.b64 %0, {%1, %2};" : "=l"(d) : "f"(lo), "f"(hi));
    return d;
}
__device__ __forceinline__ void unpack2(unsigned long long v, float& lo, float& hi) {
    asm("mov.b64 {%0, %1}, %2;" : "=f"(lo), "=f"(hi) : "l"(v));
}

// tanh(x) = 1 - 2/(exp(2x)+1) via ex2.approx + rcp.approx (~1e-6 rel err)
__device__ __forceinline__ float fast_tanh(float x) {
    float e, r;
    asm("ex2.approx.f32 %0, %1;" : "=f"(e) : "f"(x * 2.8853900817779268f));
    asm("rcp.approx.f32 %0, %1;" : "=f"(r) : "f"(e + 1.0f));
    return fmaf(-2.0f, r, 1.0f);
}

__global__ __launch_bounds__(TPB)
void metak_kernel(const int*   __restrict__ vals,
                  const float* __restrict__ dist,
                  const float* __restrict__ fc2_w1,   // [64,32]
                  const float* __restrict__ fc2_b1,   // [32]
                  const float* __restrict__ fc2_w2,   // [32,2]
                  const float* __restrict__ fc2_b2,   // [2]
                  const float* __restrict__ fc1_w1,   // [2,4]
                  const float* __restrict__ fc1_b1,   // [4]
                  const float* __restrict__ fc1_w2,   // [4,1]
                  const float* __restrict__ fc1_b2,   // [1]
                  float*       __restrict__ out)
{
    // xs: staged features; after a row's GEMV its h[32] overlays floats [0..31]
    __shared__ __align__(16) float xs[RPB * XS];    // 17408 B
    __shared__ __align__(16) float sw1[64 * 32];    // fc2_w1 staged, 8192 B
    __shared__ __align__(16) float sb1[32];
    __shared__ __align__(8)  float sw2[64];         // fc2_w2 [32][2]
    __shared__ float shead[19];  // [0..7]=f1w1 [8..11]=f1b1 [12..15]=f1w2 [16]=f1b2 [17,18]=b2

    const int tid  = threadIdx.x;
    const int lane = tid & 31;
    const int wid  = tid >> 5;
    const int rowblock = blockIdx.x * RPB;

    if (tid < RPB) {
        // ========== Phase 1: threads 0..63 each scan ONE row ==========
        const int r = rowblock + tid;
        const float4* dp = reinterpret_cast<const float4*>(dist) + (size_t)r * 8;
        const int4*   vp = reinterpret_cast<const int4*>(vals) + (size_t)r * 8;

        float4* xv = reinterpret_cast<float4*>(xs + tid * XS);

        float4 d0 = dp[0], d1 = dp[1], d2 = dp[2], d3 = dp[3],
               d4 = dp[4], d5 = dp[5], d6 = dp[6], d7 = dp[7];
        int4   v0 = vp[0], v1 = vp[1], v2 = vp[2], v3 = vp[3],
               v4 = vp[4], v5 = vp[5], v6 = vp[6], v7 = vp[7];

        xv[0] = d0; xv[1] = d1; xv[2] = d2; xv[3] = d3;
        xv[4] = d4; xv[5] = d5; xv[6] = d6; xv[7] = d7;

        // prefix distinct-nonzero-label counts (labels in [0,100); bit0 preset)
        unsigned long long m0 = 1ull, m1 = 0ull;
        int cnt = 0;
        int4 vv4[8] = {v0, v1, v2, v3, v4, v5, v6, v7};
#pragma unroll
        for (int i = 0; i < 8; i++) {
            float t0, t1, t2, t3;
#pragma unroll
            for (int e = 0; e < 4; e++) {
                int vv = (e == 0) ? vv4[i].x : (e == 1) ? vv4[i].y
                       : (e == 2) ? vv4[i].z : vv4[i].w;
                unsigned long long bit = 1ull << (vv & 63);
                bool hi = (vv & 64) != 0;
                unsigned long long cur = hi ? m1 : m0;
                cnt += (int)((cur & bit) == 0ull);
                cur |= bit;
                if (hi) m1 = cur; else m0 = cur;
                float cf = (float)cnt;
                if (e == 0) t0 = cf; else if (e == 1) t1 = cf;
                else if (e == 2) t2 = cf; else t3 = cf;
            }
            xv[8 + i] = make_float4(t0, t1, t2, t3);
        }
    } else {
        // ===== Warps 2-3 (overlapped with scan): stage weights COALESCED =====
        const int t = tid - RPB;                     // 0..63
        const float4* wsrc = reinterpret_cast<const float4*>(fc2_w1);
        float4*       wdst = reinterpret_cast<float4*>(sw1);
#pragma unroll
        for (int i = 0; i < 8; i++)
            wdst[t + 64 * i] = wsrc[t + 64 * i];     // 512 float4 total, coalesced
        if (t < 32) sb1[t] = fc2_b1[t];
        if (t < 64) sw2[t] = fc2_w2[t];              // whole range (t<64 always)
        if (t < 8)        shead[t]  = fc1_w1[t];
        else if (t < 12)  shead[t]  = fc1_b1[t - 8];
        else if (t < 16)  shead[t]  = fc1_w2[t - 12];
        else if (t == 16) shead[16] = fc1_b2[0];
        else if (t == 17) shead[17] = fc2_b2[0];
        else if (t == 18) shead[18] = fc2_b2[1];
    }

    __syncthreads();

    // ---- per-lane weight column from smem: 64 conflict-free LDS.32 ----
    unsigned long long wpk[32];
#pragma unroll
    for (int m = 0; m < 32; m++)
        wpk[m] = pack2(sw1[(2 * m) * 32 + lane],
                       sw1[(2 * m + 1) * 32 + lane]);
    const float b1 = sb1[lane];

    // ===== Phase 2a: each warp sweeps 16 rows, 2 rows x split-k = 4 chains =====
    const int wrow0 = wid * 16;
#pragma unroll 1
    for (int p = 0; p < 8; p++) {
        const int ra = wrow0 + 2 * p;
        const ulonglong2* xa = reinterpret_cast<const ulonglong2*>(xs + ra * XS);
        const ulonglong2* xb = reinterpret_cast<const ulonglong2*>(xs + (ra + 1) * XS);

        unsigned long long a0 = 0ull, a1 = 0ull, b0 = 0ull, b1c = 0ull;
#pragma unroll
        for (int c = 0; c < 8; c++) {
            ulonglong2 A0 = xa[c];                   // broadcast LDS.128
            ulonglong2 B0 = xb[c];
            ulonglong2 A1 = xa[8 + c];
            ulonglong2 B1 = xb[8 + c];
            a0  = fma2(A0.x, wpk[2 * c],      a0);
            b0  = fma2(B0.x, wpk[2 * c],      b0);
            a1  = fma2(A1.x, wpk[16 + 2 * c], a1);
            b1c = fma2(B1.x, wpk[16 + 2 * c], b1c);
            a0  = fma2(A0.y, wpk[2 * c + 1],      a0);
            b0  = fma2(B0.y, wpk[2 * c + 1],      b0);
            a1  = fma2(A1.y, wpk[16 + 2 * c + 1], a1);
            b1c = fma2(B1.y, wpk[16 + 2 * c + 1], b1c);
        }
        float x0, x1, x2, x3, y0, y1, y2, y3;
        unpack2(a0, x0, x1);
        unpack2(a1, x2, x3);
        unpack2(b0, y0, y1);
        unpack2(b1c, y2, y3);
        float hA = fast_tanh((x0 + x1) + (x2 + x3) + b1);
        float hB = fast_tanh((y0 + y1) + (y2 + y3) + b1);
        xs[ra * XS + lane]       = hA;    // overlay h into dead x region
        xs[(ra + 1) * XS + lane] = hB;
    }

    __syncwarp();   // h of this warp's rows written and read by same warp

    // ===== Phase 2b: lanes 0..15 each finish one row — no shuffles =====
    if (lane < 16) {
        const float* hrow = xs + (wrow0 + lane) * XS;
        float o0 = shead[17], o1 = shead[18];
#pragma unroll
        for (int j = 0; j < 32; j++) {
            float hj = hrow[j];
            o0 = fmaf(hj, sw2[2 * j],     o0);
            o1 = fmaf(hj, sw2[2 * j + 1], o1);
        }

        float r = shead[16];
#pragma unroll
        for (int c = 0; c < 4; c++) {
            float t = fast_tanh(fmaf(o1, shead[4 + c],
                                fmaf(o0, shead[c], shead[8 + c])));
            r = fmaf(t, shead[12 + c], r);
        }

        float* op = out + (size_t)(rowblock + wrow0 + lane) * 3;
        op[0] = o0;
        op[1] = o1;
        op[2] = r;
    }
}

extern "C" void kernel_launch(void* const* d_in, const int* in_sizes, int n_in,
                              void* d_out, int out_size)
{
    const int*   vals   = (const int*)  d_in[0];
    const float* dist   = (const float*)d_in[1];
    const float* fc2_w1 = (const float*)d_in[2];
    const float* fc2_b1 = (const float*)d_in[3];
    const float* fc2_w2 = (const float*)d_in[4];
    const float* fc2_b2 = (const float*)d_in[5];
    const float* fc1_w1 = (const float*)d_in[6];
    const float* fc1_b1 = (const float*)d_in[7];
    const float* fc1_w2 = (const float*)d_in[8];
    const float* fc1_b2 = (const float*)d_in[9];
    float* out = (float*)d_out;

    const int blocks = ROWS / RPB;   // 512
    metak_kernel<<<blocks, TPB>>>(vals, dist,
                                  fc2_w1, fc2_b1, fc2_w2, fc2_b2,
                                  fc1_w1, fc1_b1, fc1_w2, fc1_b2,
                                  out);
}

// round 16
// speedup vs baseline: 1.6600x; 1.1800x over previous
#include <cuda_runtime.h>
#include <cstdint>

#define ROWS 32768
#define TPB  128            // 4 warps
#define RPB  64             // rows per block (scanned by threads 0-63)
#define XS   68             // padded feature-row stride in smem (floats)
#define VS   36             // padded label-row stride in smem (ints)

__device__ __forceinline__ unsigned long long fma2(unsigned long long a,
                                                   unsigned long long b,
                                                   unsigned long long c) {
    unsigned long long d;
    asm("fma.rn.f32x2 %0, %1, %2, %3;" : "=l"(d) : "l"(a), "l"(b), "l"(c));
    return d;
}
__device__ __forceinline__ unsigned long long pack2(float lo, float hi) {
    unsigned long long d;
    asm("mov.b64 %0, {%1, %2};" : "=l"(d) : "f"(lo), "f"(hi));
    return d;
}
__device__ __forceinline__ void unpack2(unsigned long long v, float& lo, float& hi) {
    asm("mov.b64 {%0, %1}, %2;" : "=f"(lo), "=f"(hi) : "l"(v));
}

// tanh(x) = 1 - 2/(exp(2x)+1) via ex2.approx + rcp.approx (~1e-6 rel err)
__device__ __forceinline__ float fast_tanh(float x) {
    float e, r;
    asm("ex2.approx.f32 %0, %1;" : "=f"(e) : "f"(x * 2.8853900817779268f));
    asm("rcp.approx.f32 %0, %1;" : "=f"(r) : "f"(e + 1.0f));
    return fmaf(-2.0f, r, 1.0f);
}

__global__ __launch_bounds__(TPB)
void metak_kernel(const int*   __restrict__ vals,
                  const float* __restrict__ dist,
                  const float* __restrict__ fc2_w1,   // [64,32]
                  const float* __restrict__ fc2_b1,   // [32]
                  const float* __restrict__ fc2_w2,   // [32,2]
                  const float* __restrict__ fc2_b2,   // [2]
                  const float* __restrict__ fc1_w1,   // [2,4]
                  const float* __restrict__ fc1_b1,   // [4]
                  const float* __restrict__ fc1_w2,   // [4,1]
                  const float* __restrict__ fc1_b2,   // [1]
                  float*       __restrict__ out)
{
    __shared__ __align__(16) float xs[RPB * XS];    // features; h overlays cols 0..31
    __shared__ __align__(16) int   vb[RPB * VS];    // staged labels (padded)
    __shared__ __align__(16) float sw1[64 * 32];    // fc2_w1
    __shared__ __align__(16) float sb1[32];
    __shared__ __align__(8)  float sw2[64];         // fc2_w2 [32][2]
    __shared__ float shead[19];  // [0..7]=f1w1 [8..11]=f1b1 [12..15]=f1w2 [16]=f1b2 [17,18]=b2

    const int tid  = threadIdx.x;
    const int lane = tid & 31;
    const int wid  = tid >> 5;
    const int rowblock = blockIdx.x * RPB;

    // ===== Phase 0: fully COALESCED cooperative loads (12 LDG.128/thread) =====
    {
        const float4* dsrc = reinterpret_cast<const float4*>(dist) + (size_t)rowblock * 8;
        const int4*   vsrc = reinterpret_cast<const int4*>(vals) + (size_t)rowblock * 8;
        const float4* wsrc = reinterpret_cast<const float4*>(fc2_w1);
#pragma unroll
        for (int j = 0; j < 4; j++) {
            const int i = tid + TPB * j;             // 0..511 consecutive
            const int r = i >> 3, f = i & 7;
            float4 dv = dsrc[i];
            int4   vv = vsrc[i];
            float4 wv = wsrc[i];
            *reinterpret_cast<float4*>(xs + r * XS + f * 4) = dv;
            *reinterpret_cast<int4*>(vb + r * VS + f * 4)   = vv;
            reinterpret_cast<float4*>(sw1)[i] = wv;
        }
        if (tid < 32)       sb1[tid]  = fc2_b1[tid];
        if (tid < 64)       sw2[tid]  = fc2_w2[tid];
        if (tid < 8)        shead[tid] = fc1_w1[tid];
        else if (tid < 12)  shead[tid] = fc1_b1[tid - 8];
        else if (tid < 16)  shead[tid] = fc1_w2[tid - 12];
        else if (tid == 16) shead[16]  = fc1_b2[0];
        else if (tid == 17) shead[17]  = fc2_b2[0];
        else if (tid == 18) shead[18]  = fc2_b2[1];
    }
    __syncthreads();

    // ===== Phase 1: threads 0..63 scan ONE row each (labels from smem) =====
    if (tid < RPB) {
        const int4* vr = reinterpret_cast<const int4*>(vb + tid * VS);
        int4 vv4[8];
#pragma unroll
        for (int i = 0; i < 8; i++) vv4[i] = vr[i];

        float4* xv = reinterpret_cast<float4*>(xs + tid * XS);

        // prefix distinct-nonzero-label counts (labels in [0,100); bit0 preset)
        unsigned long long m0 = 1ull, m1 = 0ull;
        int cnt = 0;
#pragma unroll
        for (int i = 0; i < 8; i++) {
            float t0, t1, t2, t3;
#pragma unroll
            for (int e = 0; e < 4; e++) {
                int vv = (e == 0) ? vv4[i].x : (e == 1) ? vv4[i].y
                       : (e == 2) ? vv4[i].z : vv4[i].w;
                unsigned long long bit = 1ull << (vv & 63);
                bool hi = (vv & 64) != 0;
                unsigned long long cur = hi ? m1 : m0;
                cnt += (int)((cur & bit) == 0ull);
                cur |= bit;
                if (hi) m1 = cur; else m0 = cur;
                float cf = (float)cnt;
                if (e == 0) t0 = cf; else if (e == 1) t1 = cf;
                else if (e == 2) t2 = cf; else t3 = cf;
            }
            xv[8 + i] = make_float4(t0, t1, t2, t3);
        }
    }

    // ---- per-lane weight column (warps 2-3 run this while 0-1 scan) ----
    unsigned long long wpk[32];
#pragma unroll
    for (int m = 0; m < 32; m++)
        wpk[m] = pack2(sw1[(2 * m) * 32 + lane],
                       sw1[(2 * m + 1) * 32 + lane]);
    const float b1 = sb1[lane];

    __syncthreads();

    // ===== Phase 2a: each warp sweeps 16 rows, 2 rows x split-k = 4 chains =====
    const int wrow0 = wid * 16;
#pragma unroll 1
    for (int p = 0; p < 8; p++) {
        const int ra = wrow0 + 2 * p;
        const ulonglong2* xa = reinterpret_cast<const ulonglong2*>(xs + ra * XS);
        const ulonglong2* xb = reinterpret_cast<const ulonglong2*>(xs + (ra + 1) * XS);

        unsigned long long a0 = 0ull, a1 = 0ull, b0 = 0ull, b1c = 0ull;
#pragma unroll
        for (int c = 0; c < 8; c++) {
            ulonglong2 A0 = xa[c];                   // broadcast LDS.128
            ulonglong2 B0 = xb[c];
            ulonglong2 A1 = xa[8 + c];
            ulonglong2 B1 = xb[8 + c];
            a0  = fma2(A0.x, wpk[2 * c],      a0);
            b0  = fma2(B0.x, wpk[2 * c],      b0);
            a1  = fma2(A1.x, wpk[16 + 2 * c], a1);
            b1c = fma2(B1.x, wpk[16 + 2 * c], b1c);
            a0  = fma2(A0.y, wpk[2 * c + 1],      a0);
            b0  = fma2(B0.y, wpk[2 * c + 1],      b0);
            a1  = fma2(A1.y, wpk[16 + 2 * c + 1], a1);
            b1c = fma2(B1.y, wpk[16 + 2 * c + 1], b1c);
        }
        float x0, x1, x2, x3, y0, y1, y2, y3;
        unpack2(a0, x0, x1);
        unpack2(a1, x2, x3);
        unpack2(b0, y0, y1);
        unpack2(b1c, y2, y3);
        float hA = fast_tanh((x0 + x1) + (x2 + x3) + b1);
        float hB = fast_tanh((y0 + y1) + (y2 + y3) + b1);
        xs[ra * XS + lane]       = hA;    // overlay h into dead x region
        xs[(ra + 1) * XS + lane] = hB;
    }

    __syncwarp();   // h of this warp's rows written and read by same warp

    // ===== Phase 2b: lanes 0..15 each finish one row — no shuffles =====
    if (lane < 16) {
        const float* hrow = xs + (wrow0 + lane) * XS;
        float o0 = shead[17], o1 = shead[18];
#pragma unroll
        for (int j = 0; j < 32; j++) {
            float hj = hrow[j];
            o0 = fmaf(hj, sw2[2 * j],     o0);
            o1 = fmaf(hj, sw2[2 * j + 1], o1);
        }

        float r = shead[16];
#pragma unroll
        for (int c = 0; c < 4; c++) {
            float t = fast_tanh(fmaf(o1, shead[4 + c],
                                fmaf(o0, shead[c], shead[8 + c])));
            r = fmaf(t, shead[12 + c], r);
        }

        float* op = out + (size_t)(rowblock + wrow0 + lane) * 3;
        op[0] = o0;
        op[1] = o1;
        op[2] = r;
    }
}

extern "C" void kernel_launch(void* const* d_in, const int* in_sizes, int n_in,
                              void* d_out, int out_size)
{
    const int*   vals   = (const int*)  d_in[0];
    const float* dist   = (const float*)d_in[1];
    const float* fc2_w1 = (const float*)d_in[2];
    const float* fc2_b1 = (const float*)d_in[3];
    const float* fc2_w2 = (const float*)d_in[4];
    const float* fc2_b2 = (const float*)d_in[5];
    const float* fc1_w1 = (const float*)d_in[6];
    const float* fc1_b1 = (const float*)d_in[7];
    const float* fc1_w2 = (const float*)d_in[8];
    const float* fc1_b2 = (const float*)d_in[9];
    float* out = (float*)d_out;

    const int blocks = ROWS / RPB;   // 512
    metak_kernel<<<blocks, TPB>>>(vals, dist,
                                  fc2_w1, fc2_b1, fc2_w2, fc2_b2,
                                  fc1_w1, fc1_b1, fc1_w2, fc1_b2,
                                  out);
}